// round 9
// baseline (speedup 1.0000x reference)
#include <cuda_runtime.h>
#include <cuda_bf16.h>
#include <cstdint>

#define BATCH 1024
#define NB 8            // batches per CTA (MMA N)
#define NTH 512         // 16 warps
#define HID 128
#define G4  512
#define DTC 0.1f
#define Q0V 0.01f
#define RV  0.25f
#define FULL 0xffffffffu
#define AST 272         // Whh bf16 row stride in bytes (conflict-free LDSM at init)

// ---- byte offsets in dynamic smem ----
#define O_A     0         // Whh bf16 [512 rows x 272B], gate-permuted (init/LDSM only)
#define O_BF    139264    // B fragments (h bf16), 8 ksteps x 256B = 2048
#define O_WFB   141312    // Wfc bf16, fragment-permuted: 10 rows x 256B = 2560
#define O_QT    143872    // 160 floats = 640
#define O_IN    144512    // 16 floats = 64
#define O_BFC   144576    // 10 floats = 40
#define O_SIG   144616    // 80 floats = 320
#define SMEM_BYTES 144936

#define FI_QT   (O_QT / 4)
#define FI_IN   (O_IN / 4)
#define FI_BFC  (O_BFC / 4)
#define FI_SIG  (O_SIG / 4)

#define BAR_SYNC(id, cnt)   asm volatile("bar.sync %0, %1;"   :: "r"(id), "r"(cnt) : "memory")
#define BAR_ARRIVE(id, cnt) asm volatile("bar.arrive %0, %1;" :: "r"(id), "r"(cnt) : "memory")

__device__ __forceinline__ uint32_t smem_u32(const void* p) {
    uint32_t a;
    asm("{ .reg .u64 t; cvta.to.shared.u64 t, %1; cvt.u32.u64 %0, t; }" : "=r"(a) : "l"(p));
    return a;
}
__device__ __forceinline__ float tanh_ap(float x) {
    float y; asm("tanh.approx.f32 %0, %1;" : "=f"(y) : "f"(x)); return y;
}
__device__ __forceinline__ float sigm(float x) {
    return fmaf(tanh_ap(0.5f * x), 0.5f, 0.5f);
}
__device__ __forceinline__ void ldsm4(uint32_t* a, uint32_t addr) {
    asm volatile("ldmatrix.sync.aligned.m8n8.x4.shared.b16 {%0,%1,%2,%3}, [%4];"
                 : "=r"(a[0]), "=r"(a[1]), "=r"(a[2]), "=r"(a[3]) : "r"(addr));
}
__device__ __forceinline__ void mma16816(float* c, const uint32_t* a, uint32_t b0, uint32_t b1) {
    asm volatile(
        "mma.sync.aligned.m16n8k16.row.col.f32.bf16.bf16.f32 "
        "{%0,%1,%2,%3}, {%4,%5,%6,%7}, {%8,%9}, {%0,%1,%2,%3};"
        : "+f"(c[0]), "+f"(c[1]), "+f"(c[2]), "+f"(c[3])
        : "r"(a[0]), "r"(a[1]), "r"(a[2]), "r"(a[3]), "r"(b0), "r"(b1));
}
__device__ __forceinline__ __nv_bfloat162 u2b(uint32_t u) {
    return *reinterpret_cast<__nv_bfloat162*>(&u);
}

// FC partial: row r, batch b, lane-quarter q (k in [q*32, q*32+32)). bf16 from B-frags.
__device__ __forceinline__ float fc_pass(const char* smem, int r, int b, int q) {
    __nv_bfloat162 acc0 = __float2bfloat162_rn(0.f), acc1 = acc0, acc2 = acc0, acc3 = acc0;
    #pragma unroll
    for (int i = 0; i < 2; i++) {
        int ks = 2 * q + i;
        uint4 h0 = *(const uint4*)(smem + O_BF  + ks * 256 + b * 32);
        uint4 h1 = *(const uint4*)(smem + O_BF  + ks * 256 + b * 32 + 16);
        uint4 w0 = *(const uint4*)(smem + O_WFB + r * 256 + ks * 32);
        uint4 w1 = *(const uint4*)(smem + O_WFB + r * 256 + ks * 32 + 16);
        acc0 = __hfma2(u2b(h0.x), u2b(w0.x), acc0);
        acc1 = __hfma2(u2b(h0.y), u2b(w0.y), acc1);
        acc2 = __hfma2(u2b(h0.z), u2b(w0.z), acc2);
        acc3 = __hfma2(u2b(h0.w), u2b(w0.w), acc3);
        acc0 = __hfma2(u2b(h1.x), u2b(w1.x), acc0);
        acc1 = __hfma2(u2b(h1.y), u2b(w1.y), acc1);
        acc2 = __hfma2(u2b(h1.z), u2b(w1.z), acc2);
        acc3 = __hfma2(u2b(h1.w), u2b(w1.w), acc3);
    }
    float s = (__low2float(acc0) + __high2float(acc0))
            + (__low2float(acc1) + __high2float(acc1))
            + (__low2float(acc2) + __high2float(acc2))
            + (__low2float(acc3) + __high2float(acc3));
    s += __shfl_xor_sync(FULL, s, 1);
    s += __shfl_xor_sync(FULL, s, 2);
    return s;
}

// Warp-parallel Kalman predict + innovation (warp = one batch, lane e<16 = P elem e)
__device__ __forceinline__ void kpredict(
    float& Pp, float& xp0, float& xp1, float& xp2, float& xp3,
    float& iv0, float& iv1,
    float P, float x0, float x1, float x2, float x3,
    float2 z, float* smf, int lane, int b)
{
    xp0 = fmaf(DTC, x2, x0); xp1 = fmaf(DTC, x3, x1); xp2 = x2; xp3 = x3;
    float P8 = __shfl_down_sync(FULL, P, 8);
    float A  = (lane < 8) ? fmaf(DTC, P8, P) : P;
    float A2 = __shfl_down_sync(FULL, A, 2);
    float Ppv = ((lane & 3) < 2) ? fmaf(DTC, A2, A) : A;
    if (lane == 0 || lane == 5 || lane == 10 || lane == 15) Ppv += Q0V;
    Pp = Ppv;
    iv0 = z.x - xp0; iv1 = z.y - xp1;
    float Pp0 = __shfl_sync(FULL, Ppv, 0);
    float Pp5 = __shfl_sync(FULL, Ppv, 5);
    if (lane == 0) {
        smf[FI_IN + 2 * b]     = __fdividef(iv0 * iv0, Pp0 + RV);
        smf[FI_IN + 2 * b + 1] = __fdividef(iv1 * iv1, Pp5 + RV);
    }
}

__global__ void __launch_bounds__(NTH, 1) nnakf_kernel(
    const float* __restrict__ meas, const float* __restrict__ Qt,
    const float* __restrict__ Wih,  const float* __restrict__ Whh,
    const float* __restrict__ bih,  const float* __restrict__ bhh,
    const float* __restrict__ Wfc,  const float* __restrict__ bfc,
    float* __restrict__ out, int T)
{
    extern __shared__ char smem[];
    float* smf = (float*)smem;
    const uint32_t sb = smem_u32(smem);
    const int tid  = threadIdx.x;
    const int wid  = tid >> 5;
    const int lane = tid & 31;
    const int g    = lane >> 2, tq = lane & 3;

    // ---- one-time staging: Whh gate-permuted so each warp owns all 4 gates ----
    for (int idx = tid; idx < G4 * HID; idx += NTH) {
        int R = idx >> 7, k = idx & 127;
        int gate = R >> 7, hh = R & 127;
        int Rst = (hh >> 3) * 32 + gate * 8 + (hh & 7);
        *(__nv_bfloat16*)(smem + O_A + Rst * AST + k * 2) = __float2bfloat16(Whh[idx]);
    }
    // Wfc -> bf16, permuted into the SAME fragment byte order as B-frags
    for (int idx = tid; idx < 10 * HID; idx += NTH) {
        int n = idx >> 7, k = idx & 127;
        int ks = k >> 4, k2 = k & 15;
        int off = ((k2 & 7) >> 1) * 8 + (k2 >> 3) * 4 + (k2 & 1) * 2;
        *(__nv_bfloat16*)(smem + O_WFB + n * 256 + ks * 32 + off) = __float2bfloat16(Wfc[idx]);
    }
    for (int idx = tid; idx < 160; idx += NTH) smf[FI_QT + idx] = Qt[idx];
    if (tid < 10) smf[FI_BFC + tid] = bfc[tid];

    // ---- per-thread epilogue constants (hid = wid*8+g, gate o = 0..3) ----
    const int hid = wid * 8 + g;
    float bia[4], wa[4], wb[4];
    #pragma unroll
    for (int o = 0; o < 4; o++) {
        int R = o * HID + hid;
        bia[o] = bih[R] + bhh[R];
        wa[o]  = Wih[2 * R];
        wb[o]  = Wih[2 * R + 1];
    }
    __syncthreads();

    // ---- A fragments -> registers (time-invariant) ----
    const int r_lds = wid * 32 + (lane & 7) + ((lane >> 3) & 1) * 8;
    const uint32_t aA0 = sb + O_A + r_lds * AST + (lane >> 4) * 16;
    const uint32_t aA1 = aA0 + 16 * AST;
    uint32_t aF0[8][4], aF1[8][4];
    #pragma unroll
    for (int ks = 0; ks < 8; ks++) {
        ldsm4(aF0[ks], aA0 + ks * 32);
        ldsm4(aF1[ks], aA1 + ks * 32);
    }

    // B-frag store address for (hid, n=2tq)
    const int ksh = hid >> 4, k2 = hid & 15, tg = (k2 & 7) >> 1, hi = k2 >> 3, lo = k2 & 1;
    const uint32_t bfa = (uint32_t)O_BF + ksh * 256 + (2 * tq) * 32 + tg * 8 + hi * 4 + lo * 2;

    float acc0[4] = {0.f, 0.f, 0.f, 0.f}, acc1[4] = {0.f, 0.f, 0.f, 0.f};
    float c0 = 0.f, c1 = 0.f;                    // LSTM cell state in registers

    // ---- Kalman lane state (warps 0..7) ----
    float P = (lane == 0 || lane == 5 || lane == 10 || lane == 15) ? 1.0f : 0.0f;
    float x0 = 0.f, x1 = 0.f, x2 = 0.f, x3 = 0.f;
    float Pp = 0.f, xp0 = 0.f, xp1 = 0.f, xp2 = 0.f, xp3 = 0.f, iv0 = 0.f, iv1 = 0.f;
    const size_t gb = (size_t)blockIdx.x * NB + wid;

    if (wid < NB) {
        float2 z0 = *(const float2*)(meas + (size_t)gb * T * 2);
        kpredict(Pp, xp0, xp1, xp2, xp3, iv0, iv1, P, x0, x1, x2, x3,
                 z0, smf, lane, wid);
    }
    __syncthreads();   // In(0) visible; accs=0 == gates from h0=0

    for (int t = 0; t < T; t++) {
        // ---- E: epilogue + LSTM cell in registers; store h as bf16 B-frags ----
        {
            float4 inv = *(const float4*)&smf[FI_IN + 4 * tq];
            float gi0 = sigm(fmaf(wa[0], inv.x, fmaf(wb[0], inv.y, acc0[0] + bia[0])));
            float gi1 = sigm(fmaf(wa[0], inv.z, fmaf(wb[0], inv.w, acc0[1] + bia[0])));
            float gf0 = sigm(fmaf(wa[1], inv.x, fmaf(wb[1], inv.y, acc0[2] + bia[1])));
            float gf1 = sigm(fmaf(wa[1], inv.z, fmaf(wb[1], inv.w, acc0[3] + bia[1])));
            float gg0 = tanh_ap(fmaf(wa[2], inv.x, fmaf(wb[2], inv.y, acc1[0] + bia[2])));
            float gg1 = tanh_ap(fmaf(wa[2], inv.z, fmaf(wb[2], inv.w, acc1[1] + bia[2])));
            float go0 = sigm(fmaf(wa[3], inv.x, fmaf(wb[3], inv.y, acc1[2] + bia[3])));
            float go1 = sigm(fmaf(wa[3], inv.z, fmaf(wb[3], inv.w, acc1[3] + bia[3])));
            c0 = fmaf(gf0, c0, gi0 * gg0);
            c1 = fmaf(gf1, c1, gi1 * gg1);
            float h0 = go0 * tanh_ap(c0);
            float h1 = go1 * tanh_ap(c1);
            *(__nv_bfloat16*)(smem + bfa)      = __float2bfloat16(h0);
            *(__nv_bfloat16*)(smem + bfa + 32) = __float2bfloat16(h1);   // batch n+1
        }
        __syncthreads();

        // ---- M: prefetch z(t+1), MMA for gates(t+1), split FC / Kalman ----
        float2 zn = make_float2(0.f, 0.f);
        if (wid < NB && t + 1 < T)
            zn = *(const float2*)(meas + ((size_t)gb * T + t + 1) * 2);

        if (t + 1 < T) {
            #pragma unroll
            for (int u = 0; u < 4; u++) { acc0[u] = 0.f; acc1[u] = 0.f; }
            #pragma unroll
            for (int ks = 0; ks < 8; ks++) {
                uint2 bb = *(const uint2*)(smem + O_BF + ks * 256 + lane * 8);
                mma16816(acc0, aF0[ks], bb.x, bb.y);
                mma16816(acc1, aF1[ks], bb.x, bb.y);
            }
        }

        if (wid >= NB) {
            // ---- sigma-FC (bf16, from B-frags): warp = row, lane/4 = batch ----
            const int q = lane & 3, fb = lane >> 2;
            float s = fc_pass(smem, wid - NB, fb, q);
            if (q == 0)
                smf[FI_SIG + fb * 10 + (wid - NB)] = sigm(s + smf[FI_BFC + wid - NB]);
            if (wid < 10) {          // rows 8,9: second pass on warps 8,9
                float s2 = fc_pass(smem, wid, fb, q);
                if (q == 0)
                    smf[FI_SIG + fb * 10 + wid] = sigm(s2 + smf[FI_BFC + wid]);
            }
            BAR_ARRIVE(1, NTH);
        } else {
            // ---- Kalman C phase (warps 0..7) ----
            BAR_SYNC(1, NTH);    // wait for sigma
            float Ppl = Pp;
            #pragma unroll
            for (int n = 0; n < 10; n++)
                Ppl = fmaf(smf[FI_SIG + wid * 10 + n],
                           smf[FI_QT + n * 16 + (lane & 15)], Ppl);
            float s00 = __shfl_sync(FULL, Ppl, 0) + RV;
            float s01 = __shfl_sync(FULL, Ppl, 1);
            float s10 = __shfl_sync(FULL, Ppl, 4);
            float s11 = __shfl_sync(FULL, Ppl, 5) + RV;
            float det = s00 * s11 - s01 * s10;
            float rdet;
            asm("rcp.approx.f32 %0, %1;" : "=f"(rdet) : "f"(det));
            int i4 = lane & 12, j = lane & 3;
            float Pp4i  = __shfl_sync(FULL, Ppl, i4);
            float Pp4i1 = __shfl_sync(FULL, Ppl, i4 + 1);
            float Ppj   = __shfl_sync(FULL, Ppl, j);
            float Pp4j  = __shfl_sync(FULL, Ppl, 4 + j);
            float K0 = (Pp4i * s11 - Pp4i1 * s10) * rdet;
            float K1 = (Pp4i1 * s00 - Pp4i * s01) * rdet;
            P = Ppl - K0 * Ppj - K1 * Pp4j;
            float xpi = (lane >= 8) ? ((lane >= 12) ? xp3 : xp2)
                                    : ((lane >= 4) ? xp1 : xp0);
            float xn = xpi + K0 * iv0 + K1 * iv1;
            x0 = __shfl_sync(FULL, xn, 0);
            x1 = __shfl_sync(FULL, xn, 4);
            x2 = __shfl_sync(FULL, xn, 8);
            x3 = __shfl_sync(FULL, xn, 12);
            if (lane == 0)
                *(float4*)(out + ((size_t)gb * T + t) * 4) = make_float4(x0, x1, x2, x3);
            kpredict(Pp, xp0, xp1, xp2, xp3, iv0, iv1, P, x0, x1, x2, x3,
                     zn, smf, lane, wid);
        }
        __syncthreads();
    }
}

extern "C" void kernel_launch(void* const* d_in, const int* in_sizes, int n_in,
                              void* d_out, int out_size) {
    const float* meas = (const float*)d_in[0];
    const float* Qt   = (const float*)d_in[1];
    const float* Wih  = (const float*)d_in[2];
    const float* Whh  = (const float*)d_in[3];
    const float* bih  = (const float*)d_in[4];
    const float* bhh  = (const float*)d_in[5];
    const float* Wfc  = (const float*)d_in[6];
    const float* bfc  = (const float*)d_in[7];
    float* out = (float*)d_out;
    int T = in_sizes[0] / (BATCH * 2);

    cudaFuncSetAttribute(nnakf_kernel,
                         cudaFuncAttributeMaxDynamicSharedMemorySize, SMEM_BYTES);
    nnakf_kernel<<<BATCH / NB, NTH, SMEM_BYTES>>>(
        meas, Qt, Wih, Whh, bih, bhh, Wfc, bfc, out, T);
}

// round 10
// speedup vs baseline: 1.3401x; 1.3401x over previous
#include <cuda_runtime.h>
#include <cuda_bf16.h>
#include <cstdint>

#define BATCH 1024
#define NB 8            // batches per CTA (MMA N)
#define NTH 512         // 16 warps
#define HID 128
#define G4  512
#define DTC 0.1f
#define Q0V 0.01f
#define RV  0.25f
#define FULL 0xffffffffu
#define AST 272         // Whh bf16 row stride in bytes (conflict-free LDSM at init)
#define WFS 272         // Wfc frag row stride in bytes (bank-spread for row-per-lane)

// ---- byte offsets in dynamic smem ----
#define O_A     0         // Whh bf16 [512 rows x 272B], gate-permuted (init/LDSM only)
#define O_BF    139264    // B fragments (h bf16), 8 ksteps x 256B = 2048
#define O_WFB   141312    // Wfc bf16 frag-permuted, 16 rows x 272B = 4352 (rows 10-15 zero)
#define O_QT    145664    // 160 floats = 640
#define O_IN    146304    // 16 floats = 64
#define O_BFC   146368    // 16 floats = 64 (10 used, rest zero)
#define SMEM_BYTES 146432

#define FI_QT   (O_QT / 4)
#define FI_IN   (O_IN / 4)
#define FI_BFC  (O_BFC / 4)

__device__ __forceinline__ uint32_t smem_u32(const void* p) {
    uint32_t a;
    asm("{ .reg .u64 t; cvta.to.shared.u64 t, %1; cvt.u32.u64 %0, t; }" : "=r"(a) : "l"(p));
    return a;
}
__device__ __forceinline__ float tanh_ap(float x) {
    float y; asm("tanh.approx.f32 %0, %1;" : "=f"(y) : "f"(x)); return y;
}
__device__ __forceinline__ float sigm(float x) {
    return fmaf(tanh_ap(0.5f * x), 0.5f, 0.5f);
}
__device__ __forceinline__ void ldsm4(uint32_t* a, uint32_t addr) {
    asm volatile("ldmatrix.sync.aligned.m8n8.x4.shared.b16 {%0,%1,%2,%3}, [%4];"
                 : "=r"(a[0]), "=r"(a[1]), "=r"(a[2]), "=r"(a[3]) : "r"(addr));
}
__device__ __forceinline__ void mma16816(float* c, const uint32_t* a, uint32_t b0, uint32_t b1) {
    asm volatile(
        "mma.sync.aligned.m16n8k16.row.col.f32.bf16.bf16.f32 "
        "{%0,%1,%2,%3}, {%4,%5,%6,%7}, {%8,%9}, {%0,%1,%2,%3};"
        : "+f"(c[0]), "+f"(c[1]), "+f"(c[2]), "+f"(c[3])
        : "r"(a[0]), "r"(a[1]), "r"(a[2]), "r"(a[3]), "r"(b0), "r"(b1));
}
__device__ __forceinline__ __nv_bfloat162 u2b(uint32_t u) {
    return *reinterpret_cast<__nv_bfloat162*>(&u);
}

// Warp-parallel Kalman predict + innovation (warp = one batch, lane e<16 = P elem e)
__device__ __forceinline__ void kpredict(
    float& Pp, float& xp0, float& xp1, float& xp2, float& xp3,
    float& iv0, float& iv1,
    float P, float x0, float x1, float x2, float x3,
    float2 z, float* smf, int lane, int b)
{
    xp0 = fmaf(DTC, x2, x0); xp1 = fmaf(DTC, x3, x1); xp2 = x2; xp3 = x3;
    float P8 = __shfl_down_sync(FULL, P, 8);
    float A  = (lane < 8) ? fmaf(DTC, P8, P) : P;
    float A2 = __shfl_down_sync(FULL, A, 2);
    float Ppv = ((lane & 3) < 2) ? fmaf(DTC, A2, A) : A;
    if (lane == 0 || lane == 5 || lane == 10 || lane == 15) Ppv += Q0V;
    Pp = Ppv;
    iv0 = z.x - xp0; iv1 = z.y - xp1;
    float Pp0 = __shfl_sync(FULL, Ppv, 0);
    float Pp5 = __shfl_sync(FULL, Ppv, 5);
    if (lane == 0) {
        smf[FI_IN + 2 * b]     = __fdividef(iv0 * iv0, Pp0 + RV);
        smf[FI_IN + 2 * b + 1] = __fdividef(iv1 * iv1, Pp5 + RV);
    }
}

__global__ void __launch_bounds__(NTH, 1) nnakf_kernel(
    const float* __restrict__ meas, const float* __restrict__ Qt,
    const float* __restrict__ Wih,  const float* __restrict__ Whh,
    const float* __restrict__ bih,  const float* __restrict__ bhh,
    const float* __restrict__ Wfc,  const float* __restrict__ bfc,
    float* __restrict__ out, int T)
{
    extern __shared__ char smem[];
    float* smf = (float*)smem;
    const uint32_t sb = smem_u32(smem);
    const int tid  = threadIdx.x;
    const int wid  = tid >> 5;
    const int lane = tid & 31;
    const int g    = lane >> 2, tq = lane & 3;

    // ---- zero WFB + BFC regions first (racing threads -> sync before fill) ----
    for (int i = tid; i < (4352 + 64) / 4; i += NTH)
        *(uint32_t*)(smem + O_WFB + i * 4) = 0u;    // covers O_WFB..O_BFC end? (WFB 4352) then QT.. no:
    // note: O_QT..O_IN are filled below by all threads; only WFB tail + BFC need zeroing.
    __syncthreads();

    // ---- one-time staging: Whh gate-permuted so each warp owns all 4 gates ----
    for (int idx = tid; idx < G4 * HID; idx += NTH) {
        int R = idx >> 7, k = idx & 127;
        int gate = R >> 7, hh = R & 127;
        int Rst = (hh >> 3) * 32 + gate * 8 + (hh & 7);
        *(__nv_bfloat16*)(smem + O_A + Rst * AST + k * 2) = __float2bfloat16(Whh[idx]);
    }
    // Wfc -> bf16, permuted into the SAME fragment byte order as B-frags (stride WFS)
    for (int idx = tid; idx < 10 * HID; idx += NTH) {
        int n = idx >> 7, k = idx & 127;
        int ks = k >> 4, k2 = k & 15;
        int off = ((k2 & 7) >> 1) * 8 + (k2 >> 3) * 4 + (k2 & 1) * 2;
        *(__nv_bfloat16*)(smem + O_WFB + n * WFS + ks * 32 + off) = __float2bfloat16(Wfc[idx]);
    }
    for (int idx = tid; idx < 160; idx += NTH) smf[FI_QT + idx] = Qt[idx];
    if (tid < 10) smf[FI_BFC + tid] = bfc[tid];

    // ---- per-thread epilogue constants (hid = wid*8+g, gate o = 0..3) ----
    const int hid = wid * 8 + g;
    float bia[4], wa[4], wb[4];
    #pragma unroll
    for (int o = 0; o < 4; o++) {
        int R = o * HID + hid;
        bia[o] = bih[R] + bhh[R];
        wa[o]  = Wih[2 * R];
        wb[o]  = Wih[2 * R + 1];
    }
    __syncthreads();

    // ---- A fragments -> registers (time-invariant) ----
    const int r_lds = wid * 32 + (lane & 7) + ((lane >> 3) & 1) * 8;
    const uint32_t aA0 = sb + O_A + r_lds * AST + (lane >> 4) * 16;
    const uint32_t aA1 = aA0 + 16 * AST;
    uint32_t aF0[8][4], aF1[8][4];
    #pragma unroll
    for (int ks = 0; ks < 8; ks++) {
        ldsm4(aF0[ks], aA0 + ks * 32);
        ldsm4(aF1[ks], aA1 + ks * 32);
    }

    // B-frag store address for (hid, n=2tq)
    const int k2h = hid & 15, tg = (k2h & 7) >> 1, hi = k2h >> 3, lo = k2h & 1;
    const uint32_t bfa = (uint32_t)O_BF + (hid >> 4) * 256 + (2 * tq) * 32
                       + tg * 8 + hi * 4 + lo * 2;

    float acc0[4] = {0.f, 0.f, 0.f, 0.f}, acc1[4] = {0.f, 0.f, 0.f, 0.f};
    float c0 = 0.f, c1 = 0.f;                    // LSTM cell state in registers

    // ---- Kalman lane state (warps 0..7) ----
    float P = (lane == 0 || lane == 5 || lane == 10 || lane == 15) ? 1.0f : 0.0f;
    float x0 = 0.f, x1 = 0.f, x2 = 0.f, x3 = 0.f;
    float Pp = 0.f, xp0 = 0.f, xp1 = 0.f, xp2 = 0.f, xp3 = 0.f, iv0 = 0.f, iv1 = 0.f;
    const size_t gb = (size_t)blockIdx.x * NB + wid;
    const int fcr = lane >> 1, fcs = lane & 1;   // FC row / half for in-warp sigma
    const float bfcr = smf[FI_BFC + fcr];

    if (wid < NB) {
        float2 z0 = *(const float2*)(meas + (size_t)gb * T * 2);
        kpredict(Pp, xp0, xp1, xp2, xp3, iv0, iv1, P, x0, x1, x2, x3,
                 z0, smf, lane, wid);
    }
    __syncthreads();   // In(0) visible; accs=0 == gates from h0=0

    for (int t = 0; t < T; t++) {
        // ---- E: epilogue + LSTM cell in registers; store h as bf16 B-frags ----
        {
            float4 inv = *(const float4*)&smf[FI_IN + 4 * tq];
            float gi0 = sigm(fmaf(wa[0], inv.x, fmaf(wb[0], inv.y, acc0[0] + bia[0])));
            float gi1 = sigm(fmaf(wa[0], inv.z, fmaf(wb[0], inv.w, acc0[1] + bia[0])));
            float gf0 = sigm(fmaf(wa[1], inv.x, fmaf(wb[1], inv.y, acc0[2] + bia[1])));
            float gf1 = sigm(fmaf(wa[1], inv.z, fmaf(wb[1], inv.w, acc0[3] + bia[1])));
            float gg0 = tanh_ap(fmaf(wa[2], inv.x, fmaf(wb[2], inv.y, acc1[0] + bia[2])));
            float gg1 = tanh_ap(fmaf(wa[2], inv.z, fmaf(wb[2], inv.w, acc1[1] + bia[2])));
            float go0 = sigm(fmaf(wa[3], inv.x, fmaf(wb[3], inv.y, acc1[2] + bia[3])));
            float go1 = sigm(fmaf(wa[3], inv.z, fmaf(wb[3], inv.w, acc1[3] + bia[3])));
            c0 = fmaf(gf0, c0, gi0 * gg0);
            c1 = fmaf(gf1, c1, gi1 * gg1);
            float h0 = go0 * tanh_ap(c0);
            float h1 = go1 * tanh_ap(c1);
            *(__nv_bfloat16*)(smem + bfa)      = __float2bfloat16(h0);
            *(__nv_bfloat16*)(smem + bfa + 32) = __float2bfloat16(h1);   // batch n+1
        }
        __syncthreads();

        if (wid < NB) {
            // ---- in-warp sigma-FC (2 lanes per FC row, batch = wid) ----
            float2 zn = make_float2(0.f, 0.f);
            if (t + 1 < T)
                zn = *(const float2*)(meas + ((size_t)gb * T + t + 1) * 2);
            __nv_bfloat162 fa0 = __float2bfloat162_rn(0.f), fa1 = fa0, fa2 = fa0, fa3 = fa0;
            #pragma unroll
            for (int i = 0; i < 4; i++) {
                int ks = 4 * fcs + i;
                uint4 h0 = *(const uint4*)(smem + O_BF  + ks * 256 + wid * 32);
                uint4 h1 = *(const uint4*)(smem + O_BF  + ks * 256 + wid * 32 + 16);
                uint4 w0 = *(const uint4*)(smem + O_WFB + fcr * WFS + ks * 32);
                uint4 w1 = *(const uint4*)(smem + O_WFB + fcr * WFS + ks * 32 + 16);
                fa0 = __hfma2(u2b(h0.x), u2b(w0.x), fa0);
                fa1 = __hfma2(u2b(h0.y), u2b(w0.y), fa1);
                fa2 = __hfma2(u2b(h0.z), u2b(w0.z), fa2);
                fa3 = __hfma2(u2b(h0.w), u2b(w0.w), fa3);
                fa0 = __hfma2(u2b(h1.x), u2b(w1.x), fa0);
                fa1 = __hfma2(u2b(h1.y), u2b(w1.y), fa1);
                fa2 = __hfma2(u2b(h1.z), u2b(w1.z), fa2);
                fa3 = __hfma2(u2b(h1.w), u2b(w1.w), fa3);
            }
            float sgp = (__low2float(fa0) + __high2float(fa0))
                      + (__low2float(fa1) + __high2float(fa1))
                      + (__low2float(fa2) + __high2float(fa2))
                      + (__low2float(fa3) + __high2float(fa3));
            sgp += __shfl_xor_sync(FULL, sgp, 1);
            float sg = sigm(sgp + bfcr);           // valid on lanes < 20 (rows 0..9)

            // ---- Q-adapt: sigma broadcast via shfl (no smem handoff) ----
            float Ppl = Pp;
            #pragma unroll
            for (int n = 0; n < 10; n++)
                Ppl = fmaf(__shfl_sync(FULL, sg, 2 * n),
                           smf[FI_QT + n * 16 + (lane & 15)], Ppl);
            float s00 = __shfl_sync(FULL, Ppl, 0) + RV;
            float s01 = __shfl_sync(FULL, Ppl, 1);
            float s10 = __shfl_sync(FULL, Ppl, 4);
            float s11 = __shfl_sync(FULL, Ppl, 5) + RV;
            float det = s00 * s11 - s01 * s10;
            float rdet;
            asm("rcp.approx.f32 %0, %1;" : "=f"(rdet) : "f"(det));
            int i4 = lane & 12, j = lane & 3;
            float Pp4i  = __shfl_sync(FULL, Ppl, i4);
            float Pp4i1 = __shfl_sync(FULL, Ppl, i4 + 1);
            float Ppj   = __shfl_sync(FULL, Ppl, j);
            float Pp4j  = __shfl_sync(FULL, Ppl, 4 + j);
            float K0 = (Pp4i * s11 - Pp4i1 * s10) * rdet;
            float K1 = (Pp4i1 * s00 - Pp4i * s01) * rdet;
            P = Ppl - K0 * Ppj - K1 * Pp4j;
            float xpi = (lane >= 8) ? ((lane >= 12) ? xp3 : xp2)
                                    : ((lane >= 4) ? xp1 : xp0);
            float xn = xpi + K0 * iv0 + K1 * iv1;
            x0 = __shfl_sync(FULL, xn, 0);
            x1 = __shfl_sync(FULL, xn, 4);
            x2 = __shfl_sync(FULL, xn, 8);
            x3 = __shfl_sync(FULL, xn, 12);
            if (lane == 0)
                *(float4*)(out + ((size_t)gb * T + t) * 4) = make_float4(x0, x1, x2, x3);
            kpredict(Pp, xp0, xp1, xp2, xp3, iv0, iv1, P, x0, x1, x2, x3,
                     zn, smf, lane, wid);

            // ---- MMA last: HMMA latency hides behind the end barrier ----
            if (t + 1 < T) {
                #pragma unroll
                for (int u = 0; u < 4; u++) { acc0[u] = 0.f; acc1[u] = 0.f; }
                #pragma unroll
                for (int ks = 0; ks < 8; ks++) {
                    uint2 bb = *(const uint2*)(smem + O_BF + ks * 256 + lane * 8);
                    mma16816(acc0, aF0[ks], bb.x, bb.y);
                    mma16816(acc1, aF1[ks], bb.x, bb.y);
                }
            }
        } else {
            // ---- warps 8..15: MMA only, then slack for the Kalman warps ----
            if (t + 1 < T) {
                #pragma unroll
                for (int u = 0; u < 4; u++) { acc0[u] = 0.f; acc1[u] = 0.f; }
                #pragma unroll
                for (int ks = 0; ks < 8; ks++) {
                    uint2 bb = *(const uint2*)(smem + O_BF + ks * 256 + lane * 8);
                    mma16816(acc0, aF0[ks], bb.x, bb.y);
                    mma16816(acc1, aF1[ks], bb.x, bb.y);
                }
            }
        }
        __syncthreads();
    }
}

extern "C" void kernel_launch(void* const* d_in, const int* in_sizes, int n_in,
                              void* d_out, int out_size) {
    const float* meas = (const float*)d_in[0];
    const float* Qt   = (const float*)d_in[1];
    const float* Wih  = (const float*)d_in[2];
    const float* Whh  = (const float*)d_in[3];
    const float* bih  = (const float*)d_in[4];
    const float* bhh  = (const float*)d_in[5];
    const float* Wfc  = (const float*)d_in[6];
    const float* bfc  = (const float*)d_in[7];
    float* out = (float*)d_out;
    int T = in_sizes[0] / (BATCH * 2);

    cudaFuncSetAttribute(nnakf_kernel,
                         cudaFuncAttributeMaxDynamicSharedMemorySize, SMEM_BYTES);
    nnakf_kernel<<<BATCH / NB, NTH, SMEM_BYTES>>>(
        meas, Qt, Wih, Whh, bih, bhh, Wfc, bfc, out, T);
}

// round 11
// speedup vs baseline: 1.3437x; 1.0027x over previous
#include <cuda_runtime.h>
#include <cuda_bf16.h>
#include <cstdint>

#define BATCH 1024
#define NB 8            // batches per CTA (MMA N)
#define NTH 512         // 16 warps
#define HID 128
#define G4  512
#define DTC 0.1f
#define Q0V 0.01f
#define RV  0.25f
#define FULL 0xffffffffu
#define AST 272         // Whh bf16 row stride in bytes (conflict-free LDSM at init)
#define WFS 272         // Wfc frag row stride in bytes

// ---- byte offsets in dynamic smem ----
#define O_A     0         // Whh bf16 [512 rows x 272B], gate-permuted (init/LDSM only)
#define O_BF    139264    // B fragments (h bf16), 8 ksteps x 256B = 2048
#define O_WFB   141312    // Wfc bf16 frag-permuted, 16 rows x 272B = 4352 (rows 10-15 zero)
#define O_QT    145664    // 160 floats = 640
#define O_IN    146304    // 16 floats = 64
#define O_BFC   146368    // 16 floats = 64 (10 used, rest zero)
#define O_SIG   146432    // 80 floats = 320
#define SMEM_BYTES 146752

#define FI_QT   (O_QT / 4)
#define FI_IN   (O_IN / 4)
#define FI_BFC  (O_BFC / 4)
#define FI_SIG  (O_SIG / 4)

#define BAR_SYNC(id, cnt)   asm volatile("bar.sync %0, %1;"   :: "r"(id), "r"(cnt) : "memory")
#define BAR_ARRIVE(id, cnt) asm volatile("bar.arrive %0, %1;" :: "r"(id), "r"(cnt) : "memory")

__device__ __forceinline__ uint32_t smem_u32(const void* p) {
    uint32_t a;
    asm("{ .reg .u64 t; cvta.to.shared.u64 t, %1; cvt.u32.u64 %0, t; }" : "=r"(a) : "l"(p));
    return a;
}
__device__ __forceinline__ float tanh_ap(float x) {
    float y; asm("tanh.approx.f32 %0, %1;" : "=f"(y) : "f"(x)); return y;
}
__device__ __forceinline__ float sigm(float x) {
    return fmaf(tanh_ap(0.5f * x), 0.5f, 0.5f);
}
__device__ __forceinline__ void ldsm4(uint32_t* a, uint32_t addr) {
    asm volatile("ldmatrix.sync.aligned.m8n8.x4.shared.b16 {%0,%1,%2,%3}, [%4];"
                 : "=r"(a[0]), "=r"(a[1]), "=r"(a[2]), "=r"(a[3]) : "r"(addr));
}
__device__ __forceinline__ void mma16816(float* c, const uint32_t* a, uint32_t b0, uint32_t b1) {
    asm volatile(
        "mma.sync.aligned.m16n8k16.row.col.f32.bf16.bf16.f32 "
        "{%0,%1,%2,%3}, {%4,%5,%6,%7}, {%8,%9}, {%0,%1,%2,%3};"
        : "+f"(c[0]), "+f"(c[1]), "+f"(c[2]), "+f"(c[3])
        : "r"(a[0]), "r"(a[1]), "r"(a[2]), "r"(a[3]), "r"(b0), "r"(b1));
}
// first k-step: D = A*B + 0 (no accumulator init movs)
__device__ __forceinline__ void mma16816_z(float* d, const uint32_t* a, uint32_t b0, uint32_t b1) {
    asm volatile(
        "mma.sync.aligned.m16n8k16.row.col.f32.bf16.bf16.f32 "
        "{%0,%1,%2,%3}, {%4,%5,%6,%7}, {%8,%9}, {%10,%11,%12,%13};"
        : "=f"(d[0]), "=f"(d[1]), "=f"(d[2]), "=f"(d[3])
        : "r"(a[0]), "r"(a[1]), "r"(a[2]), "r"(a[3]), "r"(b0), "r"(b1),
          "f"(0.f), "f"(0.f), "f"(0.f), "f"(0.f));
}
__device__ __forceinline__ __nv_bfloat162 u2b(uint32_t u) {
    return *reinterpret_cast<__nv_bfloat162*>(&u);
}

// Warp-parallel Kalman predict + innovation (warp = one batch, lane e<16 = P elem e)
__device__ __forceinline__ void kpredict(
    float& Pp, float& xp0, float& xp1, float& xp2, float& xp3,
    float& iv0, float& iv1,
    float P, float x0, float x1, float x2, float x3,
    float2 z, float* smf, int lane, int b)
{
    xp0 = fmaf(DTC, x2, x0); xp1 = fmaf(DTC, x3, x1); xp2 = x2; xp3 = x3;
    float P8 = __shfl_down_sync(FULL, P, 8);
    float A  = (lane < 8) ? fmaf(DTC, P8, P) : P;
    float A2 = __shfl_down_sync(FULL, A, 2);
    float Ppv = ((lane & 3) < 2) ? fmaf(DTC, A2, A) : A;
    if (lane == 0 || lane == 5 || lane == 10 || lane == 15) Ppv += Q0V;
    Pp = Ppv;
    iv0 = z.x - xp0; iv1 = z.y - xp1;
    float Pp0 = __shfl_sync(FULL, Ppv, 0);
    float Pp5 = __shfl_sync(FULL, Ppv, 5);
    if (lane == 0) {
        smf[FI_IN + 2 * b]     = __fdividef(iv0 * iv0, Pp0 + RV);
        smf[FI_IN + 2 * b + 1] = __fdividef(iv1 * iv1, Pp5 + RV);
    }
}

__global__ void __launch_bounds__(NTH, 1) nnakf_kernel(
    const float* __restrict__ meas, const float* __restrict__ Qt,
    const float* __restrict__ Wih,  const float* __restrict__ Whh,
    const float* __restrict__ bih,  const float* __restrict__ bhh,
    const float* __restrict__ Wfc,  const float* __restrict__ bfc,
    float* __restrict__ out, int T)
{
    extern __shared__ char smem[];
    float* smf = (float*)smem;
    const uint32_t sb = smem_u32(smem);
    const int tid  = threadIdx.x;
    const int wid  = tid >> 5;
    const int lane = tid & 31;
    const int g    = lane >> 2, tq = lane & 3;

    // ---- zero WFB (rows 10-15 must be 0) ----
    for (int i = tid; i < 4352 / 4; i += NTH)
        *(uint32_t*)(smem + O_WFB + i * 4) = 0u;
    __syncthreads();

    // ---- one-time staging: Whh gate-permuted so each warp owns all 4 gates ----
    for (int idx = tid; idx < G4 * HID; idx += NTH) {
        int R = idx >> 7, k = idx & 127;
        int gate = R >> 7, hh = R & 127;
        int Rst = (hh >> 3) * 32 + gate * 8 + (hh & 7);
        *(__nv_bfloat16*)(smem + O_A + Rst * AST + k * 2) = __float2bfloat16(Whh[idx]);
    }
    // Wfc -> bf16, permuted into the SAME fragment byte order as B-frags
    for (int idx = tid; idx < 10 * HID; idx += NTH) {
        int n = idx >> 7, k = idx & 127;
        int ks = k >> 4, k2 = k & 15;
        int off = ((k2 & 7) >> 1) * 8 + (k2 >> 3) * 4 + (k2 & 1) * 2;
        *(__nv_bfloat16*)(smem + O_WFB + n * WFS + ks * 32 + off) = __float2bfloat16(Wfc[idx]);
    }
    for (int idx = tid; idx < 160; idx += NTH) smf[FI_QT + idx] = Qt[idx];
    if (tid < 16) smf[FI_BFC + tid] = (tid < 10) ? bfc[tid] : 0.0f;

    // ---- per-thread epilogue constants (hid = wid*8+g, gate o = 0..3) ----
    const int hid = wid * 8 + g;
    float bia[4], wa[4], wb[4];
    #pragma unroll
    for (int o = 0; o < 4; o++) {
        int R = o * HID + hid;
        bia[o] = bih[R] + bhh[R];
        wa[o]  = Wih[2 * R];
        wb[o]  = Wih[2 * R + 1];
    }
    __syncthreads();

    // ---- A fragments -> registers (time-invariant) ----
    const int r_lds = wid * 32 + (lane & 7) + ((lane >> 3) & 1) * 8;
    const uint32_t aA0 = sb + O_A + r_lds * AST + (lane >> 4) * 16;
    const uint32_t aA1 = aA0 + 16 * AST;
    uint32_t aF0[8][4], aF1[8][4];
    #pragma unroll
    for (int ks = 0; ks < 8; ks++) {
        ldsm4(aF0[ks], aA0 + ks * 32);
        ldsm4(aF1[ks], aA1 + ks * 32);
    }

    // B-frag store address for (hid, n=2tq)
    const int k2h = hid & 15, tg = (k2h & 7) >> 1, hi = k2h >> 3, lo = k2h & 1;
    const uint32_t bfa = (uint32_t)O_BF + (hid >> 4) * 256 + (2 * tq) * 32
                       + tg * 8 + hi * 4 + lo * 2;

    float acc0[4] = {0.f, 0.f, 0.f, 0.f}, acc1[4] = {0.f, 0.f, 0.f, 0.f};
    float c0 = 0.f, c1 = 0.f;                    // LSTM cell state in registers

    // ---- Kalman lane state (warps 0..7) ----
    float P = (lane == 0 || lane == 5 || lane == 10 || lane == 15) ? 1.0f : 0.0f;
    float x0 = 0.f, x1 = 0.f, x2 = 0.f, x3 = 0.f;
    float Pp = 0.f, xp0 = 0.f, xp1 = 0.f, xp2 = 0.f, xp3 = 0.f, iv0 = 0.f, iv1 = 0.f;
    const size_t gb = (size_t)blockIdx.x * NB + wid;
    const int fcr = lane >> 1, fcs = lane & 1;   // FC row / half (warps 8..15)
    const float bfcr = smf[FI_BFC + fcr];

    if (wid < NB) {
        float2 z0 = *(const float2*)(meas + (size_t)gb * T * 2);
        kpredict(Pp, xp0, xp1, xp2, xp3, iv0, iv1, P, x0, x1, x2, x3,
                 z0, smf, lane, wid);
    }
    __syncthreads();   // In(0) visible; accs=0 == gates from h0=0

    for (int t = 0; t < T; t++) {
        // ---- E: epilogue + LSTM cell in registers; store h as bf16 B-frags ----
        {
            float4 inv = *(const float4*)&smf[FI_IN + 4 * tq];
            float gi0 = sigm(fmaf(wa[0], inv.x, fmaf(wb[0], inv.y, acc0[0] + bia[0])));
            float gi1 = sigm(fmaf(wa[0], inv.z, fmaf(wb[0], inv.w, acc0[1] + bia[0])));
            float gf0 = sigm(fmaf(wa[1], inv.x, fmaf(wb[1], inv.y, acc0[2] + bia[1])));
            float gf1 = sigm(fmaf(wa[1], inv.z, fmaf(wb[1], inv.w, acc0[3] + bia[1])));
            float gg0 = tanh_ap(fmaf(wa[2], inv.x, fmaf(wb[2], inv.y, acc1[0] + bia[2])));
            float gg1 = tanh_ap(fmaf(wa[2], inv.z, fmaf(wb[2], inv.w, acc1[1] + bia[2])));
            float go0 = sigm(fmaf(wa[3], inv.x, fmaf(wb[3], inv.y, acc1[2] + bia[3])));
            float go1 = sigm(fmaf(wa[3], inv.z, fmaf(wb[3], inv.w, acc1[3] + bia[3])));
            c0 = fmaf(gf0, c0, gi0 * gg0);
            c1 = fmaf(gf1, c1, gi1 * gg1);
            float h0 = go0 * tanh_ap(c0);
            float h1 = go1 * tanh_ap(c1);
            *(__nv_bfloat16*)(smem + bfa)      = __float2bfloat16(h0);
            *(__nv_bfloat16*)(smem + bfa + 32) = __float2bfloat16(h1);   // batch n+1
        }
        __syncthreads();

        if (wid < NB) {
            // ---- warps 0..7: prefetch z, MMA (overlaps FC on w8-15), then Kalman ----
            float2 zn = make_float2(0.f, 0.f);
            if (t + 1 < T)
                zn = *(const float2*)(meas + ((size_t)gb * T + t + 1) * 2);

            if (t + 1 < T) {
                #pragma unroll
                for (int ks = 0; ks < 8; ks++) {
                    uint2 bb = *(const uint2*)(smem + O_BF + ks * 256 + lane * 8);
                    if (ks == 0) {
                        mma16816_z(acc0, aF0[0], bb.x, bb.y);
                        mma16816_z(acc1, aF1[0], bb.x, bb.y);
                    } else {
                        mma16816(acc0, aF0[ks], bb.x, bb.y);
                        mma16816(acc1, aF1[ks], bb.x, bb.y);
                    }
                }
            }
            BAR_SYNC(1, NTH);    // sigma ready (w8-15 arrived after FC)

            // ---- Q-adapt + Kalman update + predict(t+1) ----
            float Ppl = Pp;
            #pragma unroll
            for (int n = 0; n < 10; n++)
                Ppl = fmaf(smf[FI_SIG + wid * 10 + n],
                           smf[FI_QT + n * 16 + (lane & 15)], Ppl);
            float s00 = __shfl_sync(FULL, Ppl, 0) + RV;
            float s01 = __shfl_sync(FULL, Ppl, 1);
            float s10 = __shfl_sync(FULL, Ppl, 4);
            float s11 = __shfl_sync(FULL, Ppl, 5) + RV;
            float det = s00 * s11 - s01 * s10;
            float rdet;
            asm("rcp.approx.f32 %0, %1;" : "=f"(rdet) : "f"(det));
            int i4 = lane & 12, j = lane & 3;
            float Pp4i  = __shfl_sync(FULL, Ppl, i4);
            float Pp4i1 = __shfl_sync(FULL, Ppl, i4 + 1);
            float Ppj   = __shfl_sync(FULL, Ppl, j);
            float Pp4j  = __shfl_sync(FULL, Ppl, 4 + j);
            float K0 = (Pp4i * s11 - Pp4i1 * s10) * rdet;
            float K1 = (Pp4i1 * s00 - Pp4i * s01) * rdet;
            P = Ppl - K0 * Ppj - K1 * Pp4j;
            float xpi = (lane >= 8) ? ((lane >= 12) ? xp3 : xp2)
                                    : ((lane >= 4) ? xp1 : xp0);
            float xn = xpi + K0 * iv0 + K1 * iv1;
            x0 = __shfl_sync(FULL, xn, 0);
            x1 = __shfl_sync(FULL, xn, 4);
            x2 = __shfl_sync(FULL, xn, 8);
            x3 = __shfl_sync(FULL, xn, 12);
            if (lane == 0)
                *(float4*)(out + ((size_t)gb * T + t) * 4) = make_float4(x0, x1, x2, x3);
            kpredict(Pp, xp0, xp1, xp2, xp3, iv0, iv1, P, x0, x1, x2, x3,
                     zn, smf, lane, wid);
        } else {
            // ---- warps 8..15: FC FIRST (sigma for batch wid-8), arrive, then MMA ----
            const int b = wid - NB;
            __nv_bfloat162 fa0 = __float2bfloat162_rn(0.f), fa1 = fa0, fa2 = fa0, fa3 = fa0;
            #pragma unroll
            for (int i = 0; i < 4; i++) {
                int ks = 4 * fcs + i;
                uint4 h0 = *(const uint4*)(smem + O_BF  + ks * 256 + b * 32);
                uint4 h1 = *(const uint4*)(smem + O_BF  + ks * 256 + b * 32 + 16);
                uint4 w0 = *(const uint4*)(smem + O_WFB + fcr * WFS + ks * 32);
                uint4 w1 = *(const uint4*)(smem + O_WFB + fcr * WFS + ks * 32 + 16);
                fa0 = __hfma2(u2b(h0.x), u2b(w0.x), fa0);
                fa1 = __hfma2(u2b(h0.y), u2b(w0.y), fa1);
                fa2 = __hfma2(u2b(h0.z), u2b(w0.z), fa2);
                fa3 = __hfma2(u2b(h0.w), u2b(w0.w), fa3);
                fa0 = __hfma2(u2b(h1.x), u2b(w1.x), fa0);
                fa1 = __hfma2(u2b(h1.y), u2b(w1.y), fa1);
                fa2 = __hfma2(u2b(h1.z), u2b(w1.z), fa2);
                fa3 = __hfma2(u2b(h1.w), u2b(w1.w), fa3);
            }
            float sgp = (__low2float(fa0) + __high2float(fa0))
                      + (__low2float(fa1) + __high2float(fa1))
                      + (__low2float(fa2) + __high2float(fa2))
                      + (__low2float(fa3) + __high2float(fa3));
            sgp += __shfl_xor_sync(FULL, sgp, 1);
            if (fcs == 0 && fcr < 10)
                smf[FI_SIG + b * 10 + fcr] = sigm(sgp + bfcr);
            BAR_ARRIVE(1, NTH);

            if (t + 1 < T) {
                #pragma unroll
                for (int ks = 0; ks < 8; ks++) {
                    uint2 bb = *(const uint2*)(smem + O_BF + ks * 256 + lane * 8);
                    if (ks == 0) {
                        mma16816_z(acc0, aF0[0], bb.x, bb.y);
                        mma16816_z(acc1, aF1[0], bb.x, bb.y);
                    } else {
                        mma16816(acc0, aF0[ks], bb.x, bb.y);
                        mma16816(acc1, aF1[ks], bb.x, bb.y);
                    }
                }
            }
        }
        __syncthreads();
    }
}

extern "C" void kernel_launch(void* const* d_in, const int* in_sizes, int n_in,
                              void* d_out, int out_size) {
    const float* meas = (const float*)d_in[0];
    const float* Qt   = (const float*)d_in[1];
    const float* Wih  = (const float*)d_in[2];
    const float* Whh  = (const float*)d_in[3];
    const float* bih  = (const float*)d_in[4];
    const float* bhh  = (const float*)d_in[5];
    const float* Wfc  = (const float*)d_in[6];
    const float* bfc  = (const float*)d_in[7];
    float* out = (float*)d_out;
    int T = in_sizes[0] / (BATCH * 2);

    cudaFuncSetAttribute(nnakf_kernel,
                         cudaFuncAttributeMaxDynamicSharedMemorySize, SMEM_BYTES);
    nnakf_kernel<<<BATCH / NB, NTH, SMEM_BYTES>>>(
        meas, Qt, Wih, Whh, bih, bhh, Wfc, bfc, out, T);
}